// round 14
// baseline (speedup 1.0000x reference)
#include <cuda_runtime.h>
#include <cuda_bf16.h>
#include <math.h>
#include <stdint.h>

// ---------------- problem constants ----------------
constexpr int NB   = 4096;
constexpr int DIM  = 1024;
constexpr int KTOP = 10;
constexpr float ALPHA = 0.3f;

// ---------------- tiling: single-pass Gram, chained tiles ----------------
constexpr int TM = 128;
constexpr int TN = 128;
constexpr int KCHUNKS = DIM / 64;               // 16 chunks of k=64 (128B rows)
constexpr int IT = NB / TM;                     // 32 i-tiles
constexpr int JT = NB / TN;                     // 32 j-tiles
constexpr int JGROUPS = 4;                      // CTA covers 8 consecutive j-tiles
constexpr int NTILES = JT / JGROUPS;            // 8 tiles per CTA
constexpr int TOTAL_G = NTILES * KCHUNKS;       // 128 flat chunks per CTA

constexpr int STAGE_A = TM * 128;               // 16384
constexpr int STAGE_B = TN * 128;               // 16384
constexpr int STAGE_BYTES = STAGE_A + STAGE_B;  // 32768
constexpr int EPI_OFF = 4 * STAGE_BYTES;        // 131072
constexpr int EPI_STRIDE = TN + 1;              // 129 (odd -> conflict-free col scan)
constexpr int Y2_OFF  = EPI_OFF + TM * EPI_STRIDE * 4;   // 197120
constexpr int X2_OFF  = Y2_OFF + TN * 4;                 // 197632
constexpr int PRT_OFF = X2_OFF + TM * 4;                 // 198144
constexpr int SMEM_BYTES = PRT_OFF + 256 * KTOP * 4;     // 208384 (<= 232448)

// ---------------- device scratch ----------------
__device__ __align__(16) __nv_bfloat16 g_b1[NB * DIM];
__device__ __align__(16) __nv_bfloat16 g_b2[NB * DIM];
__device__ float g_x2[NB];
__device__ float g_y2[NB];
__device__ float g_diag[NB];
__device__ float g_partR[NB * JGROUPS * KTOP];  // IRR: [anchor_i][jgroup][10]
__device__ float g_partC[NB * IT * KTOP];       // RII: [anchor_j][itile][10]
__device__ float g_sum[2];
__device__ unsigned int g_zero[2];

// ---------------- PTX helpers ----------------
__device__ __forceinline__ uint32_t smem_u32(const void* p) {
    uint32_t a;
    asm("{ .reg .u64 t; cvta.to.shared.u64 t, %1; cvt.u32.u64 %0, t; }" : "=r"(a) : "l"(p));
    return a;
}
__device__ __forceinline__ void cp_async16(uint32_t saddr, const void* gaddr) {
    asm volatile("cp.async.cg.shared.global [%0], [%1], 16;" :: "r"(saddr), "l"(gaddr) : "memory");
}
__device__ __forceinline__ void cp_commit() {
    asm volatile("cp.async.commit_group;" ::: "memory");
}
__device__ __forceinline__ void cp_wait2() {
    asm volatile("cp.async.wait_group 2;" ::: "memory");
}
__device__ __forceinline__ void ldmatrix4(uint32_t* r, uint32_t addr) {
    asm volatile("ldmatrix.sync.aligned.m8n8.x4.shared.b16 {%0,%1,%2,%3}, [%4];"
                 : "=r"(r[0]), "=r"(r[1]), "=r"(r[2]), "=r"(r[3]) : "r"(addr));
}
__device__ __forceinline__ void mma_bf16(float* c, const uint32_t* a, const uint32_t* b) {
    asm volatile(
        "mma.sync.aligned.m16n8k16.row.col.f32.bf16.bf16.f32 "
        "{%0,%1,%2,%3}, {%4,%5,%6,%7}, {%8,%9}, {%0,%1,%2,%3};"
        : "+f"(c[0]), "+f"(c[1]), "+f"(c[2]), "+f"(c[3])
        : "r"(a[0]), "r"(a[1]), "r"(a[2]), "r"(a[3]), "r"(b[0]), "r"(b[1]));
}

// ---------------- fused convert + norms + counter reset ----------------
__global__ void prep_kernel(const float* __restrict__ X, const float* __restrict__ Y) {
    const int row = blockIdx.x;
    const int t = threadIdx.x;
    if (row == 0 && t < 2) { g_sum[t] = 0.f; g_zero[t] = 0u; }   // graph-replay reset

    float4 a = reinterpret_cast<const float4*>(X + (size_t)row * DIM)[t];
    float4 b = reinterpret_cast<const float4*>(Y + (size_t)row * DIM)[t];

    __nv_bfloat162* o1 = reinterpret_cast<__nv_bfloat162*>(g_b1) + (size_t)row * (DIM / 2) + t * 2;
    __nv_bfloat162* o2 = reinterpret_cast<__nv_bfloat162*>(g_b2) + (size_t)row * (DIM / 2) + t * 2;
    o1[0] = __float22bfloat162_rn(make_float2(a.x, a.y));
    o1[1] = __float22bfloat162_rn(make_float2(a.z, a.w));
    o2[0] = __float22bfloat162_rn(make_float2(b.x, b.y));
    o2[1] = __float22bfloat162_rn(make_float2(b.z, b.w));

    float sx  = a.x*a.x + a.y*a.y + a.z*a.z + a.w*a.w;
    float sy  = b.x*b.x + b.y*b.y + b.z*b.z + b.w*b.w;
    float sxy = a.x*b.x + a.y*b.y + a.z*b.z + a.w*b.w;
    #pragma unroll
    for (int o = 16; o > 0; o >>= 1) {
        sx  += __shfl_down_sync(0xffffffffu, sx,  o);
        sy  += __shfl_down_sync(0xffffffffu, sy,  o);
        sxy += __shfl_down_sync(0xffffffffu, sxy, o);
    }
    __shared__ float rs[3][8];
    int w = t >> 5, l = t & 31;
    if (l == 0) { rs[0][w] = sx; rs[1][w] = sy; rs[2][w] = sxy; }
    __syncthreads();
    if (t == 0) {
        float X2 = 0.f, Y2 = 0.f, XY = 0.f;
        #pragma unroll
        for (int q = 0; q < 8; q++) { X2 += rs[0][q]; Y2 += rs[1][q]; XY += rs[2][q]; }
        g_x2[row] = X2;
        g_y2[row] = Y2;
        g_diag[row] = sqrtf(fmaxf(X2 + Y2 - 2.f * XY, 0.f));
    }
}

// ---------------- chained-tile Gram + dual (row/col) top-10 ----------------
// grid 128 (1 wave): itile = bid>>2, jgroup = bid&3 -> j-tiles jgroup*8 .. +7
__global__ __launch_bounds__(256, 1)
void gemm_topk_kernel() {
    extern __shared__ __align__(1024) char smem[];
    const uint32_t sb = smem_u32(smem);
    float* epi = reinterpret_cast<float*>(smem + EPI_OFF);
    float* y2s = reinterpret_cast<float*>(smem + Y2_OFF);
    float* x2s = reinterpret_cast<float*>(smem + X2_OFF);
    float* prt = reinterpret_cast<float*>(smem + PRT_OFF);   // [256][10] col partials

    const int tid  = threadIdx.x;
    const int wid  = tid >> 5;
    const int lane = tid & 31;

    const int bid    = blockIdx.x;
    const int itile  = bid >> 2;
    const int jgroup = bid & 3;
    const int i0     = itile * TM;
    const int jbase  = jgroup * NTILES * TN;    // 8 consecutive j-tiles

    // warp layout: 2 (m) x 4 (n); warp tile 64x32 (proven)
    const int wm = (wid & 1) * 64;
    const int wn = (wid >> 1) * 32;
    const int laneLow  = lane & 15;
    const int laneHalf = lane >> 4;
    const int nrowb    = ((lane >> 4) & 1) * 8 + (lane & 7);
    const int khalfb   = (lane >> 3) & 1;
    const int scanIdx  = tid & 127;
    const int scanHalf = tid >> 7;

    const char* Ag = (const char*)g_b1 + (size_t)i0 * (DIM * 2);
    const char* Yb = (const char*)g_b2 + (size_t)jbase * (DIM * 2);

    // running row top-10 (IRR): s = y2_j - 2*dot, ascending, s9 = cutoff
    float s[KTOP];
    #pragma unroll
    for (int q = 0; q < KTOP; q++) s[q] = 3.0e38f;
    float s9 = s[KTOP - 1];

    if (tid < TM) x2s[tid] = g_x2[i0 + tid];    // constant across the CTA's tiles

    float acc[4][4][4];
    #pragma unroll
    for (int mi = 0; mi < 4; mi++)
        #pragma unroll
        for (int ni = 0; ni < 4; ni++)
            #pragma unroll
            for (int q = 0; q < 4; q++) acc[mi][ni][q] = 0.f;

    // flat chunk stream: g in [0,128), tile = g>>4, kc = g&15, stage = g&3
    auto issue = [&](int g) {
        if (g < TOTAL_G) {
            const int jt = g >> 4, kc = g & 15;
            const uint32_t sA = sb + (g & 3) * STAGE_BYTES;
            const uint32_t sB = sA + STAGE_A;
            const char* gA = Ag + kc * 128;
            const char* gB = Yb + (size_t)jt * TN * (DIM * 2) + kc * 128;
            #pragma unroll
            for (int e = 0; e < 4; e++) {
                int idx = tid + e * 256;       // 0..1023 = 128 rows x 8 blocks
                int row = idx >> 3;
                int b   = idx & 7;
                uint32_t so = (uint32_t)row * 128 + (uint32_t)((b ^ (row & 7)) << 4);
                cp_async16(sA + so, gA + (size_t)row * (DIM * 2) + b * 16);
                cp_async16(sB + so, gB + (size_t)row * (DIM * 2) + b * 16);
            }
        }
        cp_commit();
    };

    issue(0); issue(1); issue(2);

    for (int g = 0; g < TOTAL_G; g++) {
        cp_wait2();
        __syncthreads();
        const uint32_t sA = sb + (g & 3) * STAGE_BYTES;
        const uint32_t sB = sA + STAGE_A;
        #pragma unroll
        for (int ks = 0; ks < 4; ks++) {
            uint32_t a[4][4];
            #pragma unroll
            for (int mi = 0; mi < 4; mi++) {
                int row = wm + mi * 16 + laneLow;
                int blk = ks * 2 + laneHalf;
                ldmatrix4(a[mi], sA + (uint32_t)row * 128 + (uint32_t)((blk ^ (row & 7)) << 4));
            }
            uint32_t b[4][2];
            #pragma unroll
            for (int p = 0; p < 2; p++) {
                uint32_t r[4];
                int n = wn + p * 16 + nrowb;
                int blk = ks * 2 + khalfb;
                ldmatrix4(r, sB + (uint32_t)n * 128 + (uint32_t)((blk ^ (n & 7)) << 4));
                b[2*p][0] = r[0]; b[2*p][1] = r[1];
                b[2*p+1][0] = r[2]; b[2*p+1][1] = r[3];
            }
            #pragma unroll
            for (int mi = 0; mi < 4; mi++)
                #pragma unroll
                for (int ni = 0; ni < 4; ni++)
                    mma_bf16(acc[mi][ni], a[mi], b[ni]);
        }
        issue(g + 3);          // crosses tile boundaries: pipeline never drains

        if ((g & 15) == 15) {
            // ---- epilogue for tile jt = g>>4 (next tile's loads in flight) ----
            const int jtile = jgroup * NTILES + (g >> 4);
            const int j0    = jtile * TN;
            __syncthreads();   // prev tile's scans/flush done before epi rewrite
            #pragma unroll
            for (int mi = 0; mi < 4; mi++)
                #pragma unroll
                for (int ni = 0; ni < 4; ni++) {
                    int r0 = wm + mi * 16 + (lane >> 2);
                    int c0 = wn + ni * 8 + (lane & 3) * 2;
                    epi[r0 * EPI_STRIDE + c0]           = acc[mi][ni][0];
                    epi[r0 * EPI_STRIDE + c0 + 1]       = acc[mi][ni][1];
                    epi[(r0 + 8) * EPI_STRIDE + c0]     = acc[mi][ni][2];
                    epi[(r0 + 8) * EPI_STRIDE + c0 + 1] = acc[mi][ni][3];
                    acc[mi][ni][0] = 0.f; acc[mi][ni][1] = 0.f;
                    acc[mi][ni][2] = 0.f; acc[mi][ni][3] = 0.f;
                }
            if (tid < TN) y2s[tid] = g_y2[j0 + tid];
            __syncthreads();

            // row scan (IRR): anchor i = i0+scanIdx, cols [scanHalf*64, +64)
            {
                const float* er = epi + scanIdx * EPI_STRIDE + scanHalf * 64;
                const float* yr = y2s + scanHalf * 64;
                const int dloc = (i0 + scanIdx) - j0 - scanHalf * 64;
                #pragma unroll 4
                for (int c = 0; c < 64; c++) {
                    float v = fmaf(er[c], -2.f, yr[c]);
                    if (v < s9 && c != dloc) {
                        float w = v;
                        #pragma unroll
                        for (int q = 0; q < KTOP; q++) {
                            float sv = s[q];
                            bool lt = w < sv;
                            s[q] = lt ? w : sv;
                            w    = lt ? sv : w;
                        }
                        s9 = s[KTOP - 1];
                    }
                }
            }

            // col scan (RII): anchor j = j0+scanIdx, rows [scanHalf*64, +64); flush per tile
            {
                float sc[KTOP];
                #pragma unroll
                for (int q = 0; q < KTOP; q++) sc[q] = 3.0e38f;
                float sc9 = sc[KTOP - 1];
                const float* ec = epi + scanHalf * 64 * EPI_STRIDE + scanIdx;
                const float* xr = x2s + scanHalf * 64;
                const int dloc = (j0 + scanIdx) - i0 - scanHalf * 64;
                #pragma unroll 4
                for (int r = 0; r < 64; r++) {
                    float v = fmaf(ec[r * EPI_STRIDE], -2.f, xr[r]);
                    if (v < sc9 && r != dloc) {
                        float w = v;
                        #pragma unroll
                        for (int q = 0; q < KTOP; q++) {
                            float sv = sc[q];
                            bool lt = w < sv;
                            sc[q] = lt ? w : sv;
                            w     = lt ? sv : w;
                        }
                        sc9 = sc[KTOP - 1];
                    }
                }
                #pragma unroll
                for (int q = 0; q < KTOP; q++) prt[tid * KTOP + q] = sc[q];
            }
            __syncthreads();
            if (tid < TN) {        // merge the two half partials, flush col anchors
                float v[2 * KTOP];
                #pragma unroll
                for (int q = 0; q < KTOP; q++) {
                    v[q]        = prt[tid * KTOP + q];
                    v[KTOP + q] = prt[(tid + 128) * KTOP + q];
                }
                float* G = &g_partC[((size_t)(j0 + tid) * IT + itile) * KTOP];
                #pragma unroll
                for (int rep = 0; rep < KTOP; rep++) {
                    float m = v[0]; int mi = 0;
                    #pragma unroll
                    for (int q = 1; q < 2 * KTOP; q++)
                        if (v[q] < m) { m = v[q]; mi = q; }
                    v[mi] = 3.0e38f;
                    G[rep] = m;
                }
            }
            // next epi rewrite is guarded by the sync at the next epilogue entry
        }
    }

    // ---- flush running row top-10: merge half partials per anchor ----
    __syncthreads();
    #pragma unroll
    for (int q = 0; q < KTOP; q++) epi[tid * KTOP + q] = s[q];
    __syncthreads();
    if (tid < TM) {
        float v[2 * KTOP];
        #pragma unroll
        for (int q = 0; q < KTOP; q++) {
            v[q]        = epi[tid * KTOP + q];
            v[KTOP + q] = epi[(tid + 128) * KTOP + q];
        }
        float* P = &g_partR[((size_t)(i0 + tid) * JGROUPS + jgroup) * KTOP];
        #pragma unroll
        for (int rep = 0; rep < KTOP; rep++) {
            float m = v[0]; int mi = 0;
            #pragma unroll
            for (int q = 1; q < 2 * KTOP; q++)
                if (v[q] < m) { m = v[q]; mi = q; }
            v[mi] = 3.0e38f;
            P[rep] = m;
        }
    }
}

// ---------------- merge partials per anchor, compute cost, reduce ----------------
__global__ void merge_kernel() {
    const int idx = blockIdx.x * blockDim.x + threadIdx.x;   // 8192
    const int pass = idx >> 12;          // 0 = IRR (rows, 40 vals), 1 = RII (cols, 320 vals)
    const int i = idx & (NB - 1);
    const float* P = pass ? &g_partC[(size_t)i * IT * KTOP]
                          : &g_partR[(size_t)i * JGROUPS * KTOP];
    const int n = pass ? IT * KTOP : JGROUPS * KTOP;

    float s[KTOP];
    #pragma unroll
    for (int q = 0; q < KTOP; q++) s[q] = 3.0e38f;
    float s9 = s[KTOP - 1];
    for (int q = 0; q < n; q++) {
        float v = P[q];
        if (v < s9) {
            float w = v;
            #pragma unroll
            for (int r = 0; r < KTOP; r++) {
                float sv = s[r];
                bool lt = w < sv;
                s[r] = lt ? w : sv;
                w    = lt ? sv : w;
            }
            s9 = s[KTOP - 1];
        }
    }

    // d^2 = anchor_norm^2 + s ; IRR anchor i: x2_i ; RII anchor j: y2_j
    const float n2a = pass ? g_y2[i] : g_x2[i];
    const float dia = g_diag[i] + ALPHA;
    float sum = 0.f;
    unsigned int zc = 0;
    #pragma unroll
    for (int rep = 0; rep < KTOP; rep++) {
        float d = sqrtf(fmaxf(n2a + s[rep], 0.f));
        float c = dia - d;
        if (c > 0.f) sum += c; else zc++;
    }
    #pragma unroll
    for (int o = 16; o > 0; o >>= 1) {
        sum += __shfl_down_sync(0xffffffffu, sum, o);
        zc  += __shfl_down_sync(0xffffffffu, zc, o);
    }
    if ((threadIdx.x & 31) == 0) {
        atomicAdd(&g_sum[pass], sum);
        atomicAdd(&g_zero[pass], zc);
    }
}

__global__ void finalize_kernel(float* __restrict__ out) {
    const float inv = 1.0f / (float)(NB * KTOP);
    out[0] = g_sum[0] * inv;
    out[1] = g_sum[1] * inv;
    out[2] = (float)g_zero[0] * inv;
    out[3] = (float)g_zero[1] * inv;
}

extern "C" void kernel_launch(void* const* d_in, const int* in_sizes, int n_in,
                              void* d_out, int out_size) {
    const float* in1 = (const float*)d_in[0];
    const float* in2 = (const float*)d_in[1];
    float* out = (float*)d_out;

    cudaFuncSetAttribute(gemm_topk_kernel,
                         cudaFuncAttributeMaxDynamicSharedMemorySize, SMEM_BYTES);

    prep_kernel<<<NB, 256>>>(in1, in2);
    gemm_topk_kernel<<<IT * JGROUPS, 256, SMEM_BYTES>>>();
    merge_kernel<<<2 * NB / 256, 256>>>();
    finalize_kernel<<<1, 1>>>(out);
}

// round 16
// speedup vs baseline: 1.4075x; 1.4075x over previous
#include <cuda_runtime.h>
#include <cuda_bf16.h>
#include <math.h>
#include <stdint.h>

// ---------------- problem constants ----------------
constexpr int NB   = 4096;
constexpr int DIM  = 1024;
constexpr int KTOP = 10;
constexpr float ALPHA = 0.3f;

// ---------------- tiling: single-pass Gram, chained tiles, 1 wave ----------------
constexpr int TM = 128;
constexpr int TN = 128;
constexpr int KCHUNKS = DIM / 64;               // 16 chunks of k=64 (128B rows)
constexpr int IT = NB / TM;                     // 32 i-tiles
constexpr int JT = NB / TN;                     // 32 j-tiles
constexpr int JGROUPS = 4;                      // CTA covers 8 consecutive j-tiles
constexpr int NTILES = JT / JGROUPS;            // 8 tiles per CTA
constexpr int TOTAL_G = NTILES * KCHUNKS;       // 128 flat chunks per CTA

constexpr int STAGE_A = TM * 128;               // 16384
constexpr int STAGE_B = TN * 128;               // 16384
constexpr int STAGE_BYTES = STAGE_A + STAGE_B;  // 32768
constexpr int EPI_OFF = 4 * STAGE_BYTES;        // 131072
constexpr int EPI_STRIDE = TN + 1;              // 129 (odd -> conflict-free col scan)
constexpr int Y2_OFF  = EPI_OFF + TM * EPI_STRIDE * 4;   // 197120
constexpr int X2_OFF  = Y2_OFF + TN * 4;                 // 197632
constexpr int SMEM_BYTES = X2_OFF + TM * 4;              // 198144 (<= 232448)

// ---------------- device scratch ----------------
__device__ __align__(16) __nv_bfloat16 g_b1[NB * DIM];
__device__ __align__(16) __nv_bfloat16 g_b2[NB * DIM];
__device__ float g_x2[NB];
__device__ float g_y2[NB];
__device__ float g_diag[NB];
__device__ float g_partR[NB * JGROUPS * 2 * KTOP];  // IRR: [i][jgroup][half][10]
__device__ float g_partC[NB * IT * 2 * KTOP];       // RII: [j][itile][half][10]
__device__ float g_sum[2];
__device__ unsigned int g_zero[2];

// ---------------- PTX helpers ----------------
__device__ __forceinline__ uint32_t smem_u32(const void* p) {
    uint32_t a;
    asm("{ .reg .u64 t; cvta.to.shared.u64 t, %1; cvt.u32.u64 %0, t; }" : "=r"(a) : "l"(p));
    return a;
}
__device__ __forceinline__ void cp_async16(uint32_t saddr, const void* gaddr) {
    asm volatile("cp.async.cg.shared.global [%0], [%1], 16;" :: "r"(saddr), "l"(gaddr) : "memory");
}
__device__ __forceinline__ void cp_commit() {
    asm volatile("cp.async.commit_group;" ::: "memory");
}
__device__ __forceinline__ void cp_wait2() {
    asm volatile("cp.async.wait_group 2;" ::: "memory");
}
__device__ __forceinline__ void ldmatrix4(uint32_t* r, uint32_t addr) {
    asm volatile("ldmatrix.sync.aligned.m8n8.x4.shared.b16 {%0,%1,%2,%3}, [%4];"
                 : "=r"(r[0]), "=r"(r[1]), "=r"(r[2]), "=r"(r[3]) : "r"(addr));
}
__device__ __forceinline__ void mma_bf16(float* c, const uint32_t* a, const uint32_t* b) {
    asm volatile(
        "mma.sync.aligned.m16n8k16.row.col.f32.bf16.bf16.f32 "
        "{%0,%1,%2,%3}, {%4,%5,%6,%7}, {%8,%9}, {%0,%1,%2,%3};"
        : "+f"(c[0]), "+f"(c[1]), "+f"(c[2]), "+f"(c[3])
        : "r"(a[0]), "r"(a[1]), "r"(a[2]), "r"(a[3]), "r"(b[0]), "r"(b[1]));
}

// ---------------- fused convert + norms + counter reset ----------------
__global__ void prep_kernel(const float* __restrict__ X, const float* __restrict__ Y) {
    const int row = blockIdx.x;
    const int t = threadIdx.x;
    if (row == 0 && t < 2) { g_sum[t] = 0.f; g_zero[t] = 0u; }   // graph-replay reset

    float4 a = reinterpret_cast<const float4*>(X + (size_t)row * DIM)[t];
    float4 b = reinterpret_cast<const float4*>(Y + (size_t)row * DIM)[t];

    __nv_bfloat162* o1 = reinterpret_cast<__nv_bfloat162*>(g_b1) + (size_t)row * (DIM / 2) + t * 2;
    __nv_bfloat162* o2 = reinterpret_cast<__nv_bfloat162*>(g_b2) + (size_t)row * (DIM / 2) + t * 2;
    o1[0] = __float22bfloat162_rn(make_float2(a.x, a.y));
    o1[1] = __float22bfloat162_rn(make_float2(a.z, a.w));
    o2[0] = __float22bfloat162_rn(make_float2(b.x, b.y));
    o2[1] = __float22bfloat162_rn(make_float2(b.z, b.w));

    float sx  = a.x*a.x + a.y*a.y + a.z*a.z + a.w*a.w;
    float sy  = b.x*b.x + b.y*b.y + b.z*b.z + b.w*b.w;
    float sxy = a.x*b.x + a.y*b.y + a.z*b.z + a.w*b.w;
    #pragma unroll
    for (int o = 16; o > 0; o >>= 1) {
        sx  += __shfl_down_sync(0xffffffffu, sx,  o);
        sy  += __shfl_down_sync(0xffffffffu, sy,  o);
        sxy += __shfl_down_sync(0xffffffffu, sxy, o);
    }
    __shared__ float rs[3][8];
    int w = t >> 5, l = t & 31;
    if (l == 0) { rs[0][w] = sx; rs[1][w] = sy; rs[2][w] = sxy; }
    __syncthreads();
    if (t == 0) {
        float X2 = 0.f, Y2 = 0.f, XY = 0.f;
        #pragma unroll
        for (int q = 0; q < 8; q++) { X2 += rs[0][q]; Y2 += rs[1][q]; XY += rs[2][q]; }
        g_x2[row] = X2;
        g_y2[row] = Y2;
        g_diag[row] = sqrtf(fmaxf(X2 + Y2 - 2.f * XY, 0.f));
    }
}

// ---------------- chained-tile Gram + dual top-10, raw partial flush ----------------
// grid 128 (1 wave): itile = bid>>2, jgroup = bid&3 -> j-tiles jgroup*8 .. +7
__global__ __launch_bounds__(256, 1)
void gemm_topk_kernel() {
    extern __shared__ __align__(1024) char smem[];
    const uint32_t sb = smem_u32(smem);
    float* epi = reinterpret_cast<float*>(smem + EPI_OFF);
    float* y2s = reinterpret_cast<float*>(smem + Y2_OFF);
    float* x2s = reinterpret_cast<float*>(smem + X2_OFF);

    const int tid  = threadIdx.x;
    const int wid  = tid >> 5;
    const int lane = tid & 31;

    const int bid    = blockIdx.x;
    const int itile  = bid >> 2;
    const int jgroup = bid & 3;
    const int i0     = itile * TM;
    const int jbase  = jgroup * NTILES * TN;

    // warp layout: 2 (m) x 4 (n); warp tile 64x32 (proven)
    const int wm = (wid & 1) * 64;
    const int wn = (wid >> 1) * 32;
    const int laneLow  = lane & 15;
    const int laneHalf = lane >> 4;
    const int nrowb    = ((lane >> 4) & 1) * 8 + (lane & 7);
    const int khalfb   = (lane >> 3) & 1;
    const int scanIdx  = tid & 127;
    const int scanHalf = tid >> 7;

    const char* Ag = (const char*)g_b1 + (size_t)i0 * (DIM * 2);
    const char* Yb = (const char*)g_b2 + (size_t)jbase * (DIM * 2);

    // running row top-10 (IRR): s = y2_j - 2*dot, ascending, s9 = cutoff
    float s[KTOP];
    #pragma unroll
    for (int q = 0; q < KTOP; q++) s[q] = 3.0e38f;
    float s9 = s[KTOP - 1];

    if (tid < TM) x2s[tid] = g_x2[i0 + tid];    // constant across the CTA's tiles

    float acc[4][4][4];
    #pragma unroll
    for (int mi = 0; mi < 4; mi++)
        #pragma unroll
        for (int ni = 0; ni < 4; ni++)
            #pragma unroll
            for (int q = 0; q < 4; q++) acc[mi][ni][q] = 0.f;

    // flat chunk stream: g in [0,128), tile = g>>4, kc = g&15, stage = g&3
    auto issue = [&](int g) {
        if (g < TOTAL_G) {
            const int jt = g >> 4, kc = g & 15;
            const uint32_t sA = sb + (g & 3) * STAGE_BYTES;
            const uint32_t sB = sA + STAGE_A;
            const char* gA = Ag + kc * 128;
            const char* gB = Yb + (size_t)jt * TN * (DIM * 2) + kc * 128;
            #pragma unroll
            for (int e = 0; e < 4; e++) {
                int idx = tid + e * 256;       // 0..1023 = 128 rows x 8 blocks
                int row = idx >> 3;
                int b   = idx & 7;
                uint32_t so = (uint32_t)row * 128 + (uint32_t)((b ^ (row & 7)) << 4);
                cp_async16(sA + so, gA + (size_t)row * (DIM * 2) + b * 16);
                cp_async16(sB + so, gB + (size_t)row * (DIM * 2) + b * 16);
            }
        }
        cp_commit();
    };

    issue(0); issue(1); issue(2);

    for (int g = 0; g < TOTAL_G; g++) {
        cp_wait2();
        __syncthreads();
        const uint32_t sA = sb + (g & 3) * STAGE_BYTES;
        const uint32_t sB = sA + STAGE_A;
        #pragma unroll
        for (int ks = 0; ks < 4; ks++) {
            uint32_t a[4][4];
            #pragma unroll
            for (int mi = 0; mi < 4; mi++) {
                int row = wm + mi * 16 + laneLow;
                int blk = ks * 2 + laneHalf;
                ldmatrix4(a[mi], sA + (uint32_t)row * 128 + (uint32_t)((blk ^ (row & 7)) << 4));
            }
            uint32_t b[4][2];
            #pragma unroll
            for (int p = 0; p < 2; p++) {
                uint32_t r[4];
                int n = wn + p * 16 + nrowb;
                int blk = ks * 2 + khalfb;
                ldmatrix4(r, sB + (uint32_t)n * 128 + (uint32_t)((blk ^ (n & 7)) << 4));
                b[2*p][0] = r[0]; b[2*p][1] = r[1];
                b[2*p+1][0] = r[2]; b[2*p+1][1] = r[3];
            }
            #pragma unroll
            for (int mi = 0; mi < 4; mi++)
                #pragma unroll
                for (int ni = 0; ni < 4; ni++)
                    mma_bf16(acc[mi][ni], a[mi], b[ni]);
        }
        issue(g + 3);          // crosses tile boundaries: pipeline never drains

        if ((g & 15) == 15) {
            // ---- epilogue for tile jt = g>>4 (next tile's loads in flight) ----
            const int jtile = jgroup * NTILES + (g >> 4);
            const int j0    = jtile * TN;
            __syncthreads();   // prev tile's scans done reading epi/y2s
            #pragma unroll
            for (int mi = 0; mi < 4; mi++)
                #pragma unroll
                for (int ni = 0; ni < 4; ni++) {
                    int r0 = wm + mi * 16 + (lane >> 2);
                    int c0 = wn + ni * 8 + (lane & 3) * 2;
                    epi[r0 * EPI_STRIDE + c0]           = acc[mi][ni][0];
                    epi[r0 * EPI_STRIDE + c0 + 1]       = acc[mi][ni][1];
                    epi[(r0 + 8) * EPI_STRIDE + c0]     = acc[mi][ni][2];
                    epi[(r0 + 8) * EPI_STRIDE + c0 + 1] = acc[mi][ni][3];
                    acc[mi][ni][0] = 0.f; acc[mi][ni][1] = 0.f;
                    acc[mi][ni][2] = 0.f; acc[mi][ni][3] = 0.f;
                }
            if (tid < TN) y2s[tid] = g_y2[j0 + tid];
            __syncthreads();

            // row scan (IRR): anchor i = i0+scanIdx, cols [scanHalf*64, +64)
            {
                const float* er = epi + scanIdx * EPI_STRIDE + scanHalf * 64;
                const float* yr = y2s + scanHalf * 64;
                const int dloc = (i0 + scanIdx) - j0 - scanHalf * 64;
                #pragma unroll 4
                for (int c = 0; c < 64; c++) {
                    float v = fmaf(er[c], -2.f, yr[c]);
                    if (v < s9 && c != dloc) {
                        float w = v;
                        #pragma unroll
                        for (int q = 0; q < KTOP; q++) {
                            float sv = s[q];
                            bool lt = w < sv;
                            s[q] = lt ? w : sv;
                            w    = lt ? sv : w;
                        }
                        s9 = s[KTOP - 1];
                    }
                }
            }

            // col scan (RII): anchor j = j0+scanIdx, rows [scanHalf*64, +64);
            // raw flush per (tile, half) -> no merge, no staging, no extra sync
            {
                float sc[KTOP];
                #pragma unroll
                for (int q = 0; q < KTOP; q++) sc[q] = 3.0e38f;
                float sc9 = sc[KTOP - 1];
                const float* ec = epi + scanHalf * 64 * EPI_STRIDE + scanIdx;
                const float* xr = x2s + scanHalf * 64;
                const int dloc = (j0 + scanIdx) - i0 - scanHalf * 64;
                #pragma unroll 4
                for (int r = 0; r < 64; r++) {
                    float v = fmaf(ec[r * EPI_STRIDE], -2.f, xr[r]);
                    if (v < sc9 && r != dloc) {
                        float w = v;
                        #pragma unroll
                        for (int q = 0; q < KTOP; q++) {
                            float sv = sc[q];
                            bool lt = w < sv;
                            sc[q] = lt ? w : sv;
                            w     = lt ? sv : w;
                        }
                        sc9 = sc[KTOP - 1];
                    }
                }
                float* G = &g_partC[(((size_t)(j0 + scanIdx) * IT + itile) * 2 + scanHalf) * KTOP];
                #pragma unroll
                for (int q = 0; q < KTOP; q++) G[q] = sc[q];
            }
            // next tile's epi/y2s rewrite guarded by the sync at the next epilogue entry
        }
    }

    // ---- raw flush of running row top-10 (both halves, no merge) ----
    {
        float* P = &g_partR[(((size_t)(i0 + scanIdx) * JGROUPS + jgroup) * 2 + scanHalf) * KTOP];
        #pragma unroll
        for (int q = 0; q < KTOP; q++) P[q] = s[q];
    }
}

// ---------------- merge raw partials per anchor, compute cost, reduce ----------------
__global__ void merge_kernel() {
    const int idx = blockIdx.x * blockDim.x + threadIdx.x;   // 8192
    const int pass = idx >> 12;          // 0 = IRR (80 vals), 1 = RII (640 vals)
    const int i = idx & (NB - 1);
    const float* P = pass ? &g_partC[(size_t)i * IT * 2 * KTOP]
                          : &g_partR[(size_t)i * JGROUPS * 2 * KTOP];
    const int n = pass ? IT * 2 * KTOP : JGROUPS * 2 * KTOP;

    float s[KTOP];
    #pragma unroll
    for (int q = 0; q < KTOP; q++) s[q] = 3.0e38f;
    float s9 = s[KTOP - 1];
    for (int q = 0; q < n; q++) {
        float v = P[q];
        if (v < s9) {
            float w = v;
            #pragma unroll
            for (int r = 0; r < KTOP; r++) {
                float sv = s[r];
                bool lt = w < sv;
                s[r] = lt ? w : sv;
                w    = lt ? sv : w;
            }
            s9 = s[KTOP - 1];
        }
    }

    // d^2 = anchor_norm^2 + s ; IRR anchor i: x2_i ; RII anchor j: y2_j
    const float n2a = pass ? g_y2[i] : g_x2[i];
    const float dia = g_diag[i] + ALPHA;
    float sum = 0.f;
    unsigned int zc = 0;
    #pragma unroll
    for (int rep = 0; rep < KTOP; rep++) {
        float d = sqrtf(fmaxf(n2a + s[rep], 0.f));
        float c = dia - d;
        if (c > 0.f) sum += c; else zc++;
    }
    #pragma unroll
    for (int o = 16; o > 0; o >>= 1) {
        sum += __shfl_down_sync(0xffffffffu, sum, o);
        zc  += __shfl_down_sync(0xffffffffu, zc, o);
    }
    if ((threadIdx.x & 31) == 0) {
        atomicAdd(&g_sum[pass], sum);
        atomicAdd(&g_zero[pass], zc);
    }
}

__global__ void finalize_kernel(float* __restrict__ out) {
    const float inv = 1.0f / (float)(NB * KTOP);
    out[0] = g_sum[0] * inv;
    out[1] = g_sum[1] * inv;
    out[2] = (float)g_zero[0] * inv;
    out[3] = (float)g_zero[1] * inv;
}

extern "C" void kernel_launch(void* const* d_in, const int* in_sizes, int n_in,
                              void* d_out, int out_size) {
    const float* in1 = (const float*)d_in[0];
    const float* in2 = (const float*)d_in[1];
    float* out = (float*)d_out;

    cudaFuncSetAttribute(gemm_topk_kernel,
                         cudaFuncAttributeMaxDynamicSharedMemorySize, SMEM_BYTES);

    prep_kernel<<<NB, 256>>>(in1, in2);
    gemm_topk_kernel<<<IT * JGROUPS, 256, SMEM_BYTES>>>();
    merge_kernel<<<2 * NB / 256, 256>>>();
    finalize_kernel<<<1, 1>>>(out);
}

// round 17
// speedup vs baseline: 1.9482x; 1.3842x over previous
#include <cuda_runtime.h>
#include <cuda_bf16.h>
#include <math.h>
#include <stdint.h>

// ---------------- problem constants ----------------
constexpr int NB   = 4096;
constexpr int DIM  = 1024;
constexpr int KTOP = 10;
constexpr float ALPHA = 0.3f;

// ---------------- tiling ----------------
constexpr int TM = 128;
constexpr int TN = 128;
constexpr int KCHUNKS = DIM / 64;               // 16 chunks of k=64 (128B rows)
constexpr int IT = NB / TM;                     // 32
constexpr int JGROUPS = 4;                      // CTA covers 8 consecutive j-tiles
constexpr int NTILES = (NB / TN) / JGROUPS;     // 8
constexpr int TOTAL_G = NTILES * KCHUNKS;       // 128 flat chunks per CTA

constexpr int STAGE_A = TM * 128;
constexpr int STAGE_B = TN * 128;
constexpr int STAGE_BYTES = STAGE_A + STAGE_B;  // 32768
constexpr int SMEM_BYTES = 4 * STAGE_BYTES;     // 131072

constexpr int NSTRIPS = 8;                      // 512-value strips per anchor

// ---------------- device scratch ----------------
__device__ __align__(16) __nv_bfloat16 g_b1[NB * DIM];
__device__ __align__(16) __nv_bfloat16 g_b2[NB * DIM];
__device__ __align__(16) float g_D[(size_t)NB * NB];   // raw dot products (64 MB)
__device__ float g_x2[NB];
__device__ float g_y2[NB];
__device__ float g_diag[NB];
__device__ float g_partR[NB * NSTRIPS * KTOP];  // IRR: [i][strip][10]
__device__ float g_partC[NB * NSTRIPS * KTOP];  // RII: [j][strip][10]
__device__ float g_sum[2];
__device__ unsigned int g_zero[2];

// ---------------- PTX helpers ----------------
__device__ __forceinline__ uint32_t smem_u32(const void* p) {
    uint32_t a;
    asm("{ .reg .u64 t; cvta.to.shared.u64 t, %1; cvt.u32.u64 %0, t; }" : "=r"(a) : "l"(p));
    return a;
}
__device__ __forceinline__ void cp_async16(uint32_t saddr, const void* gaddr) {
    asm volatile("cp.async.cg.shared.global [%0], [%1], 16;" :: "r"(saddr), "l"(gaddr) : "memory");
}
__device__ __forceinline__ void cp_commit() {
    asm volatile("cp.async.commit_group;" ::: "memory");
}
__device__ __forceinline__ void cp_wait2() {
    asm volatile("cp.async.wait_group 2;" ::: "memory");
}
__device__ __forceinline__ void ldmatrix4(uint32_t* r, uint32_t addr) {
    asm volatile("ldmatrix.sync.aligned.m8n8.x4.shared.b16 {%0,%1,%2,%3}, [%4];"
                 : "=r"(r[0]), "=r"(r[1]), "=r"(r[2]), "=r"(r[3]) : "r"(addr));
}
__device__ __forceinline__ void mma_bf16(float* c, const uint32_t* a, const uint32_t* b) {
    asm volatile(
        "mma.sync.aligned.m16n8k16.row.col.f32.bf16.bf16.f32 "
        "{%0,%1,%2,%3}, {%4,%5,%6,%7}, {%8,%9}, {%0,%1,%2,%3};"
        : "+f"(c[0]), "+f"(c[1]), "+f"(c[2]), "+f"(c[3])
        : "r"(a[0]), "r"(a[1]), "r"(a[2]), "r"(a[3]), "r"(b[0]), "r"(b[1]));
}

// ---------------- fused convert + norms + counter reset ----------------
__global__ void prep_kernel(const float* __restrict__ X, const float* __restrict__ Y) {
    const int row = blockIdx.x;
    const int t = threadIdx.x;
    if (row == 0 && t < 2) { g_sum[t] = 0.f; g_zero[t] = 0u; }   // graph-replay reset

    float4 a = reinterpret_cast<const float4*>(X + (size_t)row * DIM)[t];
    float4 b = reinterpret_cast<const float4*>(Y + (size_t)row * DIM)[t];

    __nv_bfloat162* o1 = reinterpret_cast<__nv_bfloat162*>(g_b1) + (size_t)row * (DIM / 2) + t * 2;
    __nv_bfloat162* o2 = reinterpret_cast<__nv_bfloat162*>(g_b2) + (size_t)row * (DIM / 2) + t * 2;
    o1[0] = __float22bfloat162_rn(make_float2(a.x, a.y));
    o1[1] = __float22bfloat162_rn(make_float2(a.z, a.w));
    o2[0] = __float22bfloat162_rn(make_float2(b.x, b.y));
    o2[1] = __float22bfloat162_rn(make_float2(b.z, b.w));

    float sx  = a.x*a.x + a.y*a.y + a.z*a.z + a.w*a.w;
    float sy  = b.x*b.x + b.y*b.y + b.z*b.z + b.w*b.w;
    float sxy = a.x*b.x + a.y*b.y + a.z*b.z + a.w*b.w;
    #pragma unroll
    for (int o = 16; o > 0; o >>= 1) {
        sx  += __shfl_down_sync(0xffffffffu, sx,  o);
        sy  += __shfl_down_sync(0xffffffffu, sy,  o);
        sxy += __shfl_down_sync(0xffffffffu, sxy, o);
    }
    __shared__ float rs[3][8];
    int w = t >> 5, l = t & 31;
    if (l == 0) { rs[0][w] = sx; rs[1][w] = sy; rs[2][w] = sxy; }
    __syncthreads();
    if (t == 0) {
        float X2 = 0.f, Y2 = 0.f, XY = 0.f;
        #pragma unroll
        for (int q = 0; q < 8; q++) { X2 += rs[0][q]; Y2 += rs[1][q]; XY += rs[2][q]; }
        g_x2[row] = X2;
        g_y2[row] = Y2;
        g_diag[row] = sqrtf(fmaxf(X2 + Y2 - 2.f * XY, 0.f));
    }
}

// ---------------- pure GEMM: chained tiles, direct STG epilogue ----------------
// grid 128 (1 wave): itile = bid>>2, jgroup = bid&3 -> j-tiles jgroup*8 .. +7
__global__ __launch_bounds__(256, 1)
void gemm_kernel() {
    extern __shared__ __align__(1024) char smem[];
    const uint32_t sb = smem_u32(smem);

    const int tid  = threadIdx.x;
    const int wid  = tid >> 5;
    const int lane = tid & 31;

    const int bid    = blockIdx.x;
    const int itile  = bid >> 2;
    const int jgroup = bid & 3;
    const int i0     = itile * TM;
    const int jbase  = jgroup * NTILES * TN;

    // warp layout: 2 (m) x 4 (n); warp tile 64x32 (proven)
    const int wm = (wid & 1) * 64;
    const int wn = (wid >> 1) * 32;
    const int laneLow  = lane & 15;
    const int laneHalf = lane >> 4;
    const int nrowb    = ((lane >> 4) & 1) * 8 + (lane & 7);
    const int khalfb   = (lane >> 3) & 1;

    const char* Ag = (const char*)g_b1 + (size_t)i0 * (DIM * 2);
    const char* Yb = (const char*)g_b2 + (size_t)jbase * (DIM * 2);

    float acc[4][4][4];
    #pragma unroll
    for (int mi = 0; mi < 4; mi++)
        #pragma unroll
        for (int ni = 0; ni < 4; ni++)
            #pragma unroll
            for (int q = 0; q < 4; q++) acc[mi][ni][q] = 0.f;

    // flat chunk stream: g in [0,128), tile = g>>4, kc = g&15, stage = g&3
    auto issue = [&](int g) {
        if (g < TOTAL_G) {
            const int jt = g >> 4, kc = g & 15;
            const uint32_t sA = sb + (g & 3) * STAGE_BYTES;
            const uint32_t sB = sA + STAGE_A;
            const char* gA = Ag + kc * 128;
            const char* gB = Yb + (size_t)jt * TN * (DIM * 2) + kc * 128;
            #pragma unroll
            for (int e = 0; e < 4; e++) {
                int idx = tid + e * 256;       // 0..1023 = 128 rows x 8 blocks
                int row = idx >> 3;
                int b   = idx & 7;
                uint32_t so = (uint32_t)row * 128 + (uint32_t)((b ^ (row & 7)) << 4);
                cp_async16(sA + so, gA + (size_t)row * (DIM * 2) + b * 16);
                cp_async16(sB + so, gB + (size_t)row * (DIM * 2) + b * 16);
            }
        }
        cp_commit();
    };

    issue(0); issue(1); issue(2);

    for (int g = 0; g < TOTAL_G; g++) {
        cp_wait2();
        __syncthreads();
        const uint32_t sA = sb + (g & 3) * STAGE_BYTES;
        const uint32_t sB = sA + STAGE_A;
        #pragma unroll
        for (int ks = 0; ks < 4; ks++) {
            uint32_t a[4][4];
            #pragma unroll
            for (int mi = 0; mi < 4; mi++) {
                int row = wm + mi * 16 + laneLow;
                int blk = ks * 2 + laneHalf;
                ldmatrix4(a[mi], sA + (uint32_t)row * 128 + (uint32_t)((blk ^ (row & 7)) << 4));
            }
            uint32_t b[4][2];
            #pragma unroll
            for (int p = 0; p < 2; p++) {
                uint32_t r[4];
                int n = wn + p * 16 + nrowb;
                int blk = ks * 2 + khalfb;
                ldmatrix4(r, sB + (uint32_t)n * 128 + (uint32_t)((blk ^ (n & 7)) << 4));
                b[2*p][0] = r[0]; b[2*p][1] = r[1];
                b[2*p+1][0] = r[2]; b[2*p+1][1] = r[3];
            }
            #pragma unroll
            for (int mi = 0; mi < 4; mi++)
                #pragma unroll
                for (int ni = 0; ni < 4; ni++)
                    mma_bf16(acc[mi][ni], a[mi], b[ni]);
        }
        issue(g + 3);          // crosses tile boundaries: pipeline never drains

        if ((g & 15) == 15) {
            // ---- epilogue: direct STG.64 from registers, zero acc; NO syncs ----
            const int j0 = jbase + (g >> 4) * TN;
            #pragma unroll
            for (int mi = 0; mi < 4; mi++)
                #pragma unroll
                for (int ni = 0; ni < 4; ni++) {
                    int r0 = wm + mi * 16 + (lane >> 2);
                    int c0 = wn + ni * 8 + (lane & 3) * 2;
                    size_t base = (size_t)(i0 + r0) * NB + (j0 + c0);
                    *reinterpret_cast<float2*>(g_D + base) =
                        make_float2(acc[mi][ni][0], acc[mi][ni][1]);
                    *reinterpret_cast<float2*>(g_D + base + (size_t)8 * NB) =
                        make_float2(acc[mi][ni][2], acc[mi][ni][3]);
                    acc[mi][ni][0] = 0.f; acc[mi][ni][1] = 0.f;
                    acc[mi][ni][2] = 0.f; acc[mi][ni][3] = 0.f;
                }
        }
    }
}

// ---------------- scan kernel: dual top-10 over D ----------------
// grid 256: bid<128 row scan (IRR), bid>=128 col scan (RII)
__global__ __launch_bounds__(256)
void scan_kernel() {
    __shared__ float nrm[NB];        // 16 KB: y2 (rows) or x2 (cols)
    const int tid = threadIdx.x;
    const int bid = blockIdx.x;
    const bool isCol = bid >= 128;

    {   // cooperative norm load
        const float* src = isCol ? g_x2 : g_y2;
        const float4* s4 = reinterpret_cast<const float4*>(src);
        float4* d4 = reinterpret_cast<float4*>(nrm);
        #pragma unroll
        for (int e = 0; e < NB / 4 / 256; e++) d4[tid + e * 256] = s4[tid + e * 256];
    }
    __syncthreads();

    float s[KTOP];
    #pragma unroll
    for (int q = 0; q < KTOP; q++) s[q] = 3.0e38f;
    float s9 = s[KTOP - 1];

    if (!isCol) {
        // row scan: task = bid*256+tid; anchor i = task>>3, strip = task&7 (512 cols)
        const int task  = bid * 256 + tid;
        const int i     = task >> 3;
        const int strip = task & 7;
        const int cbase = strip * 512;
        const float4* Dp = reinterpret_cast<const float4*>(g_D + (size_t)i * NB + cbase);
        const float* yb = nrm + cbase;
        const int dloc = i - cbase;            // diagonal local col if in [0,512)
        #pragma unroll 4
        for (int c4 = 0; c4 < 128; c4++) {
            float4 d = Dp[c4];
            float vv[4] = {
                fmaf(d.x, -2.f, yb[c4 * 4 + 0]),
                fmaf(d.y, -2.f, yb[c4 * 4 + 1]),
                fmaf(d.z, -2.f, yb[c4 * 4 + 2]),
                fmaf(d.w, -2.f, yb[c4 * 4 + 3])};
            #pragma unroll
            for (int k = 0; k < 4; k++) {
                if (vv[k] < s9 && (c4 * 4 + k) != dloc) {
                    float w = vv[k];
                    #pragma unroll
                    for (int q = 0; q < KTOP; q++) {
                        float sv = s[q];
                        bool lt = w < sv;
                        s[q] = lt ? w : sv;
                        w    = lt ? sv : w;
                    }
                    s9 = s[KTOP - 1];
                }
            }
        }
        float* P = &g_partR[((size_t)i * NSTRIPS + strip) * KTOP];
        #pragma unroll
        for (int q = 0; q < KTOP; q++) P[q] = s[q];
    } else {
        // col scan: cb = bid-128; anchor j = cb*32 + lane; warp w rows [w*512,+512)
        const int cb   = bid - 128;
        const int w    = tid >> 5;
        const int lane = tid & 31;
        const int j    = cb * 32 + lane;
        const int r0   = w * 512;
        const float* Dp = g_D + (size_t)r0 * NB + j;
        #pragma unroll 8
        for (int r = 0; r < 512; r++) {
            float v = fmaf(Dp[(size_t)r * NB], -2.f, nrm[r0 + r]);
            if (v < s9 && (r0 + r) != j) {
                float ww = v;
                #pragma unroll
                for (int q = 0; q < KTOP; q++) {
                    float sv = s[q];
                    bool lt = ww < sv;
                    s[q] = lt ? ww : sv;
                    ww   = lt ? sv : ww;
                }
                s9 = s[KTOP - 1];
            }
        }
        float* P = &g_partC[((size_t)j * NSTRIPS + w) * KTOP];
        #pragma unroll
        for (int q = 0; q < KTOP; q++) P[q] = s[q];
    }
}

// ---------------- merge 80 partials per anchor, compute cost, reduce ----------------
__global__ void merge_kernel() {
    const int idx = blockIdx.x * blockDim.x + threadIdx.x;   // 8192
    const int pass = idx >> 12;          // 0 = IRR (rows), 1 = RII (cols)
    const int i = idx & (NB - 1);
    const float* P = pass ? &g_partC[(size_t)i * NSTRIPS * KTOP]
                          : &g_partR[(size_t)i * NSTRIPS * KTOP];

    float s[KTOP];
    #pragma unroll
    for (int q = 0; q < KTOP; q++) s[q] = 3.0e38f;
    float s9 = s[KTOP - 1];
    #pragma unroll 2
    for (int q = 0; q < NSTRIPS * KTOP; q++) {
        float v = P[q];
        if (v < s9) {
            float w = v;
            #pragma unroll
            for (int r = 0; r < KTOP; r++) {
                float sv = s[r];
                bool lt = w < sv;
                s[r] = lt ? w : sv;
                w    = lt ? sv : w;
            }
            s9 = s[KTOP - 1];
        }
    }

    // d^2 = anchor_norm^2 + s ; IRR anchor i: x2_i ; RII anchor j: y2_j
    const float n2a = pass ? g_y2[i] : g_x2[i];
    const float dia = g_diag[i] + ALPHA;
    float sum = 0.f;
    unsigned int zc = 0;
    #pragma unroll
    for (int rep = 0; rep < KTOP; rep++) {
        float d = sqrtf(fmaxf(n2a + s[rep], 0.f));
        float c = dia - d;
        if (c > 0.f) sum += c; else zc++;
    }
    #pragma unroll
    for (int o = 16; o > 0; o >>= 1) {
        sum += __shfl_down_sync(0xffffffffu, sum, o);
        zc  += __shfl_down_sync(0xffffffffu, zc, o);
    }
    if ((threadIdx.x & 31) == 0) {
        atomicAdd(&g_sum[pass], sum);
        atomicAdd(&g_zero[pass], zc);
    }
}

__global__ void finalize_kernel(float* __restrict__ out) {
    const float inv = 1.0f / (float)(NB * KTOP);
    out[0] = g_sum[0] * inv;
    out[1] = g_sum[1] * inv;
    out[2] = (float)g_zero[0] * inv;
    out[3] = (float)g_zero[1] * inv;
}

extern "C" void kernel_launch(void* const* d_in, const int* in_sizes, int n_in,
                              void* d_out, int out_size) {
    const float* in1 = (const float*)d_in[0];
    const float* in2 = (const float*)d_in[1];
    float* out = (float*)d_out;

    cudaFuncSetAttribute(gemm_kernel,
                         cudaFuncAttributeMaxDynamicSharedMemorySize, SMEM_BYTES);

    prep_kernel<<<NB, 256>>>(in1, in2);
    gemm_kernel<<<IT * JGROUPS, 256, SMEM_BYTES>>>();
    scan_kernel<<<256, 256>>>();
    merge_kernel<<<2 * NB / 256, 256>>>();
    finalize_kernel<<<1, 1>>>(out);
}